// round 1
// baseline (speedup 1.0000x reference)
#include <cuda_runtime.h>
#include <cstdint>

#define B_    256
#define T_    1024
#define IN_   3
#define HID_  512
#define RANK_ 4
#define OUT_  3

#define TPB 128   // 4 warps per block (one block per batch element)
#define UPT 4     // hidden units per thread (contiguous -> float4 stores)

// tanh via hardware EX2 + RCP approx: tanh(x) = (e^{2x}-1)/(e^{2x}+1).
// abs error ~1e-7 over the full range; recurrence is contracting (|J|~0.33)
// so this cannot compound.
__device__ __forceinline__ float tanh_fast(float x) {
    float xc = fminf(fmaxf(x, -15.0f), 15.0f);
    float e;
    asm("ex2.approx.f32 %0, %1;" : "=f"(e) : "f"(xc * 2.8853901f)); // 2*log2(e)
    float r;
    asm("rcp.approx.f32 %0, %1;" : "=f"(r) : "f"(e + 1.0f));
    return (e - 1.0f) * r;
}

__global__ void __launch_bounds__(TPB)
low_rank_rnn_kernel(const float* __restrict__ x,
                    const float* __restrict__ hidden,
                    const float* __restrict__ U,
                    const float* __restrict__ V,
                    const float* __restrict__ Win,
                    const float* __restrict__ bin,
                    const float* __restrict__ Wout,
                    const float* __restrict__ bout,
                    float* __restrict__ out,    // [B,T,OUT]
                    float* __restrict__ hlast,  // [B,HID]
                    float* __restrict__ rout)   // [B,T,HID]
{
    const int b   = blockIdx.x;
    const int tid = threadIdx.x;
    const int wid = tid >> 5;
    const int j0  = tid * UPT;

    __shared__ float xs[T_ * IN_];                       // 12 KB: whole x[b]
    __shared__ __align__(16) float red[2][4][8];         // ping-pong cross-warp buf

    // ---- stage x[b] into smem ----
    const float* xb = x + (size_t)b * (T_ * IN_);
    #pragma unroll 1
    for (int i = tid; i < T_ * IN_; i += TPB) xs[i] = xb[i];

    // ---- per-thread weights into registers ----
    float u[RANK_][UPT], v[RANK_][UPT], wo[OUT_][UPT], wi[UPT][IN_], bi[UPT];
    #pragma unroll
    for (int r = 0; r < RANK_; r++)
        #pragma unroll
        for (int k = 0; k < UPT; k++) {
            u[r][k] = U[r * HID_ + j0 + k];
            v[r][k] = V[r * HID_ + j0 + k];
        }
    #pragma unroll
    for (int o = 0; o < OUT_; o++)
        #pragma unroll
        for (int k = 0; k < UPT; k++) wo[o][k] = Wout[o * HID_ + j0 + k];
    #pragma unroll
    for (int k = 0; k < UPT; k++) {
        #pragma unroll
        for (int i = 0; i < IN_; i++) wi[k][i] = Win[(j0 + k) * IN_ + i];
        bi[k] = bin[j0 + k];
    }
    float bo0 = 0.f, bo1 = 0.f, bo2 = 0.f;
    if (tid == 0) { bo0 = bout[0]; bo1 = bout[1]; bo2 = bout[2]; }

    float h[UPT];
    #pragma unroll
    for (int k = 0; k < UPT; k++) h[k] = hidden[(size_t)b * HID_ + j0 + k];

    // ---- initial p = V @ h (uses red[1]; loop step t uses red[t&1]) ----
    {
        float pp0 = 0.f, pp1 = 0.f, pp2 = 0.f, pp3 = 0.f;
        #pragma unroll
        for (int k = 0; k < UPT; k++) {
            pp0 = fmaf(h[k], v[0][k], pp0);
            pp1 = fmaf(h[k], v[1][k], pp1);
            pp2 = fmaf(h[k], v[2][k], pp2);
            pp3 = fmaf(h[k], v[3][k], pp3);
        }
        #pragma unroll
        for (int off = 16; off > 0; off >>= 1) {
            pp0 += __shfl_xor_sync(0xffffffffu, pp0, off);
            pp1 += __shfl_xor_sync(0xffffffffu, pp1, off);
            pp2 += __shfl_xor_sync(0xffffffffu, pp2, off);
            pp3 += __shfl_xor_sync(0xffffffffu, pp3, off);
        }
        if ((tid & 31) == 0) {
            red[1][wid][0] = pp0; red[1][wid][1] = pp1;
            red[1][wid][2] = pp2; red[1][wid][3] = pp3;
        }
    }
    __syncthreads();   // also covers xs staging

    float4 a0 = *(const float4*)&red[1][0][0];
    float4 a1 = *(const float4*)&red[1][1][0];
    float4 a2 = *(const float4*)&red[1][2][0];
    float4 a3 = *(const float4*)&red[1][3][0];
    float p0 = a0.x + a1.x + a2.x + a3.x;
    float p1 = a0.y + a1.y + a2.y + a3.y;
    float p2 = a0.z + a1.z + a2.z + a3.z;
    float p3 = a0.w + a1.w + a2.w + a3.w;

    // ---- precompute iw for t=0 ----
    float iw[UPT];
    {
        float x0 = xs[0], x1 = xs[1], x2 = xs[2];
        #pragma unroll
        for (int k = 0; k < UPT; k++)
            iw[k] = fmaf(x2, wi[k][2], fmaf(x1, wi[k][1], fmaf(x0, wi[k][0], bi[k])));
    }

    float* routb = rout + (size_t)b * T_ * HID_;
    float* outb  = out  + (size_t)b * T_ * OUT_;

    #pragma unroll 1
    for (int t = 0; t < T_; t++) {
        const int pb = t & 1;

        // a = iw + U^T p ; h = tanh(a); partial p' = V h, q = Wout h
        float pp0 = 0.f, pp1 = 0.f, pp2 = 0.f, pp3 = 0.f;
        float q0 = 0.f, q1 = 0.f, q2 = 0.f;
        #pragma unroll
        for (int k = 0; k < UPT; k++) {
            float a = iw[k];
            a = fmaf(p0, u[0][k], a);
            a = fmaf(p1, u[1][k], a);
            a = fmaf(p2, u[2][k], a);
            a = fmaf(p3, u[3][k], a);
            float hh = tanh_fast(a);
            h[k] = hh;
            pp0 = fmaf(hh, v[0][k], pp0);
            pp1 = fmaf(hh, v[1][k], pp1);
            pp2 = fmaf(hh, v[2][k], pp2);
            pp3 = fmaf(hh, v[3][k], pp3);
            q0  = fmaf(hh, wo[0][k], q0);
            q1  = fmaf(hh, wo[1][k], q1);
            q2  = fmaf(hh, wo[2][k], q2);
        }

        // coalesced r_out store (128 threads x float4 = contiguous 2 KB row)
        *(float4*)(routb + (size_t)t * HID_ + j0) =
            make_float4(h[0], h[1], h[2], h[3]);

        // warp butterfly over 7 values
        #pragma unroll
        for (int off = 16; off > 0; off >>= 1) {
            pp0 += __shfl_xor_sync(0xffffffffu, pp0, off);
            pp1 += __shfl_xor_sync(0xffffffffu, pp1, off);
            pp2 += __shfl_xor_sync(0xffffffffu, pp2, off);
            pp3 += __shfl_xor_sync(0xffffffffu, pp3, off);
            q0  += __shfl_xor_sync(0xffffffffu, q0,  off);
            q1  += __shfl_xor_sync(0xffffffffu, q1,  off);
            q2  += __shfl_xor_sync(0xffffffffu, q2,  off);
        }
        if ((tid & 31) == 0) {
            red[pb][wid][0] = pp0; red[pb][wid][1] = pp1;
            red[pb][wid][2] = pp2; red[pb][wid][3] = pp3;
            red[pb][wid][4] = q0;  red[pb][wid][5] = q1;
            red[pb][wid][6] = q2;
        }

        // prefetch next iw (independent of p) in the barrier shadow
        if (t + 1 < T_) {
            float x0 = xs[3 * (t + 1) + 0];
            float x1 = xs[3 * (t + 1) + 1];
            float x2 = xs[3 * (t + 1) + 2];
            #pragma unroll
            for (int k = 0; k < UPT; k++)
                iw[k] = fmaf(x2, wi[k][2], fmaf(x1, wi[k][1], fmaf(x0, wi[k][0], bi[k])));
        }

        __syncthreads();   // single barrier per step (ping-pong removes the 2nd)

        float4 c0 = *(const float4*)&red[pb][0][0];
        float4 c1 = *(const float4*)&red[pb][1][0];
        float4 c2 = *(const float4*)&red[pb][2][0];
        float4 c3 = *(const float4*)&red[pb][3][0];
        p0 = c0.x + c1.x + c2.x + c3.x;
        p1 = c0.y + c1.y + c2.y + c3.y;
        p2 = c0.z + c1.z + c2.z + c3.z;
        p3 = c0.w + c1.w + c2.w + c3.w;

        if (tid == 0) {
            float o0 = red[pb][0][4] + red[pb][1][4] + red[pb][2][4] + red[pb][3][4] + bo0;
            float o1 = red[pb][0][5] + red[pb][1][5] + red[pb][2][5] + red[pb][3][5] + bo1;
            float o2 = red[pb][0][6] + red[pb][1][6] + red[pb][2][6] + red[pb][3][6] + bo2;
            outb[(size_t)t * OUT_ + 0] = o0;
            outb[(size_t)t * OUT_ + 1] = o1;
            outb[(size_t)t * OUT_ + 2] = o2;
        }
    }

    // h_last
    *(float4*)(hlast + (size_t)b * HID_ + j0) = make_float4(h[0], h[1], h[2], h[3]);
}

extern "C" void kernel_launch(void* const* d_in, const int* in_sizes, int n_in,
                              void* d_out, int out_size) {
    const float* x      = (const float*)d_in[0];
    const float* hidden = (const float*)d_in[1];
    const float* U      = (const float*)d_in[2];
    const float* V      = (const float*)d_in[3];
    const float* Win    = (const float*)d_in[4];
    const float* bin    = (const float*)d_in[5];
    const float* Wout   = (const float*)d_in[6];
    const float* bout   = (const float*)d_in[7];

    float* out   = (float*)d_out;                       // [B,T,OUT]
    float* hlast = out   + (size_t)B_ * T_ * OUT_;      // [B,HID]
    float* rout  = hlast + (size_t)B_ * HID_;           // [B,T,HID]

    low_rank_rnn_kernel<<<B_, TPB>>>(x, hidden, U, V, Win, bin, Wout, bout,
                                     out, hlast, rout);
}

// round 3
// speedup vs baseline: 1.2077x; 1.2077x over previous
#include <cuda_runtime.h>
#include <cstdint>

#define B_    256
#define T_    1024
#define IN_   3
#define HID_  512
#define RANK_ 4
#define OUT_  3

#define TPB 64    // 2 warps per block (one block per batch element)
#define UPT 8     // hidden units per thread -> 4 f32x2 pairs, 2 float4 stores

typedef unsigned long long u64;

// Packed f32x2 FMA (ptxas never auto-fuses; must use PTX fma.rn.f32x2).
__device__ __forceinline__ u64 fma2(u64 a, u64 b, u64 c) {
    u64 d;
    asm("fma.rn.f32x2 %0, %1, %2, %3;" : "=l"(d) : "l"(a), "l"(b), "l"(c));
    return d;
}
__device__ __forceinline__ u64 pack2(float lo, float hi) {
    u64 r;
    asm("mov.b64 %0, {%1, %2};" : "=l"(r) : "f"(lo), "f"(hi));
    return r;
}
__device__ __forceinline__ void unpack2(u64 v, float& lo, float& hi) {
    asm("mov.b64 {%0, %1}, %2;" : "=f"(lo), "=f"(hi) : "l"(v));
}
__device__ __forceinline__ float hadd2(u64 v) {
    float lo, hi;
    unpack2(v, lo, hi);
    return lo + hi;
}

// Exact-enough tanh: 1 - 2/(e^{2x}+1). 5 instrs, chain ~44 cyc, err ~1e-7.
// No clamp needed: ex2(huge)->inf->rcp->0->1; ex2(-huge)->0->rcp(1)=1->-1.
__device__ __forceinline__ float tanh_fast(float x) {
    float e;
    asm("ex2.approx.f32 %0, %1;" : "=f"(e) : "f"(x * 2.8853901f)); // 2*log2(e)
    float r;
    asm("rcp.approx.f32 %0, %1;" : "=f"(r) : "f"(e + 1.0f));
    return fmaf(-2.0f, r, 1.0f);
}

__global__ void __launch_bounds__(TPB)
low_rank_rnn_kernel(const float* __restrict__ x,
                    const float* __restrict__ hidden,
                    const float* __restrict__ U,
                    const float* __restrict__ V,
                    const float* __restrict__ Win,
                    const float* __restrict__ bin,
                    const float* __restrict__ Wout,
                    const float* __restrict__ bout,
                    float* __restrict__ out,    // [B,T,OUT]
                    float* __restrict__ hlast,  // [B,HID]
                    float* __restrict__ rout)   // [B,T,HID]
{
    const int b    = blockIdx.x;
    const int tid  = threadIdx.x;
    const int wid  = tid >> 5;
    const int lane = tid & 31;
    const int j0   = tid * UPT;

    // 8 writer slots per buffer: wid*4 + lane/8, each slot = 8 floats
    // [0..3]=p partials, [4..6]=q partials
    __shared__ float xs[T_ * IN_];                   // 12 KB: whole x[b]
    __shared__ __align__(16) float red[2][8][8];     // ping-pong cross-warp buf

    const bool writer  = (lane & 7) == 0;
    const int  wslot   = wid * 4 + (lane >> 3);

    // ---- stage x[b] into smem (vectorized) ----
    {
        const float4* xb4 = (const float4*)(x + (size_t)b * (T_ * IN_));
        float4* xs4 = (float4*)xs;
        #pragma unroll 1
        for (int i = tid; i < (T_ * IN_) / 4; i += TPB) xs4[i] = xb4[i];
    }

    // ---- per-thread weights, packed over unit pairs ----
    u64 up[RANK_][4], vp[RANK_][4], wop[OUT_][4], wip[IN_][4], bip[4];
    #pragma unroll
    for (int r = 0; r < RANK_; r++)
        #pragma unroll
        for (int pp = 0; pp < 4; pp++) {
            up[r][pp] = pack2(U[r * HID_ + j0 + 2 * pp], U[r * HID_ + j0 + 2 * pp + 1]);
            vp[r][pp] = pack2(V[r * HID_ + j0 + 2 * pp], V[r * HID_ + j0 + 2 * pp + 1]);
        }
    #pragma unroll
    for (int o = 0; o < OUT_; o++)
        #pragma unroll
        for (int pp = 0; pp < 4; pp++)
            wop[o][pp] = pack2(Wout[o * HID_ + j0 + 2 * pp], Wout[o * HID_ + j0 + 2 * pp + 1]);
    #pragma unroll
    for (int i = 0; i < IN_; i++)
        #pragma unroll
        for (int pp = 0; pp < 4; pp++)
            wip[i][pp] = pack2(Win[(j0 + 2 * pp) * IN_ + i], Win[(j0 + 2 * pp + 1) * IN_ + i]);
    #pragma unroll
    for (int pp = 0; pp < 4; pp++)
        bip[pp] = pack2(bin[j0 + 2 * pp], bin[j0 + 2 * pp + 1]);

    float bo0 = 0.f, bo1 = 0.f, bo2 = 0.f;
    if (tid == 0) { bo0 = bout[0]; bo1 = bout[1]; bo2 = bout[2]; }

    float h[UPT];
    #pragma unroll
    for (int k = 0; k < UPT; k++) h[k] = hidden[(size_t)b * HID_ + j0 + k];

    // ---- initial p = V @ h (into red[1]; loop t=0 writes red[0]) ----
    {
        u64 acc[RANK_] = {0ull, 0ull, 0ull, 0ull};
        #pragma unroll
        for (int pp = 0; pp < 4; pp++) {
            u64 hp = pack2(h[2 * pp], h[2 * pp + 1]);
            #pragma unroll
            for (int r = 0; r < RANK_; r++) acc[r] = fma2(hp, vp[r][pp], acc[r]);
        }
        float s0 = hadd2(acc[0]), s1 = hadd2(acc[1]);
        float s2 = hadd2(acc[2]), s3 = hadd2(acc[3]);
        #pragma unroll
        for (int off = 1; off <= 4; off <<= 1) {
            s0 += __shfl_xor_sync(0xffffffffu, s0, off);
            s1 += __shfl_xor_sync(0xffffffffu, s1, off);
            s2 += __shfl_xor_sync(0xffffffffu, s2, off);
            s3 += __shfl_xor_sync(0xffffffffu, s3, off);
        }
        if (writer)
            *(float4*)&red[1][wslot][0] = make_float4(s0, s1, s2, s3);
    }
    __syncthreads();   // also covers xs staging

    float p0, p1, p2, p3;
    {
        float4 c0 = *(const float4*)&red[1][0][0];
        float4 c1 = *(const float4*)&red[1][1][0];
        float4 c2 = *(const float4*)&red[1][2][0];
        float4 c3 = *(const float4*)&red[1][3][0];
        float4 c4 = *(const float4*)&red[1][4][0];
        float4 c5 = *(const float4*)&red[1][5][0];
        float4 c6 = *(const float4*)&red[1][6][0];
        float4 c7 = *(const float4*)&red[1][7][0];
        p0 = ((c0.x + c1.x) + (c2.x + c3.x)) + ((c4.x + c5.x) + (c6.x + c7.x));
        p1 = ((c0.y + c1.y) + (c2.y + c3.y)) + ((c4.y + c5.y) + (c6.y + c7.y));
        p2 = ((c0.z + c1.z) + (c2.z + c3.z)) + ((c4.z + c5.z) + (c6.z + c7.z));
        p3 = ((c0.w + c1.w) + (c2.w + c3.w)) + ((c4.w + c5.w) + (c6.w + c7.w));
    }

    // ---- iw for t=0 (packed) ----
    u64 iw[4];
    {
        u64 x0 = pack2(xs[0], xs[0]);
        u64 x1 = pack2(xs[1], xs[1]);
        u64 x2 = pack2(xs[2], xs[2]);
        #pragma unroll
        for (int pp = 0; pp < 4; pp++)
            iw[pp] = fma2(x2, wip[2][pp], fma2(x1, wip[1][pp], fma2(x0, wip[0][pp], bip[pp])));
    }

    float* routb = rout + (size_t)b * T_ * HID_;
    float* outb  = out  + (size_t)b * T_ * OUT_;

    #pragma unroll 1
    for (int t = 0; t < T_; t++) {
        const int pb = t & 1;

        // a = iw + U^T p (packed)
        u64 pB0 = pack2(p0, p0), pB1 = pack2(p1, p1);
        u64 pB2 = pack2(p2, p2), pB3 = pack2(p3, p3);
        u64 a[4];
        #pragma unroll
        for (int pp = 0; pp < 4; pp++)
            a[pp] = fma2(pB3, up[3][pp], fma2(pB2, up[2][pp],
                    fma2(pB1, up[1][pp], fma2(pB0, up[0][pp], iw[pp]))));

        // h = tanh(a)
        #pragma unroll
        for (int pp = 0; pp < 4; pp++) {
            float a0, a1;
            unpack2(a[pp], a0, a1);
            h[2 * pp]     = tanh_fast(a0);
            h[2 * pp + 1] = tanh_fast(a1);
        }

        // partial p' = V h, q = Wout h (packed accumulation + horizontal add)
        u64 pa[RANK_] = {0ull, 0ull, 0ull, 0ull};
        u64 qa[OUT_]  = {0ull, 0ull, 0ull};
        #pragma unroll
        for (int pp = 0; pp < 4; pp++) {
            u64 hp = pack2(h[2 * pp], h[2 * pp + 1]);
            #pragma unroll
            for (int r = 0; r < RANK_; r++) pa[r] = fma2(hp, vp[r][pp], pa[r]);
            #pragma unroll
            for (int o = 0; o < OUT_; o++)  qa[o] = fma2(hp, wop[o][pp], qa[o]);
        }
        float s0 = hadd2(pa[0]), s1 = hadd2(pa[1]);
        float s2 = hadd2(pa[2]), s3 = hadd2(pa[3]);
        float t0 = hadd2(qa[0]), t1 = hadd2(qa[1]), t2 = hadd2(qa[2]);

        // coalesced r_out store (off the dependency chain)
        *(float4*)(routb + (size_t)t * HID_ + j0)     = make_float4(h[0], h[1], h[2], h[3]);
        *(float4*)(routb + (size_t)t * HID_ + j0 + 4) = make_float4(h[4], h[5], h[6], h[7]);

        // 3-level butterfly: lanes within groups of 8 share the sum
        #pragma unroll
        for (int off = 1; off <= 4; off <<= 1) {
            s0 += __shfl_xor_sync(0xffffffffu, s0, off);
            s1 += __shfl_xor_sync(0xffffffffu, s1, off);
            s2 += __shfl_xor_sync(0xffffffffu, s2, off);
            s3 += __shfl_xor_sync(0xffffffffu, s3, off);
            t0 += __shfl_xor_sync(0xffffffffu, t0, off);
            t1 += __shfl_xor_sync(0xffffffffu, t1, off);
            t2 += __shfl_xor_sync(0xffffffffu, t2, off);
        }
        if (writer) {
            *(float4*)&red[pb][wslot][0] = make_float4(s0, s1, s2, s3);
            *(float4*)&red[pb][wslot][4] = make_float4(t0, t1, t2, 0.f);
        }

        // prefetch next iw (independent of p) in the barrier shadow
        if (t + 1 < T_) {
            u64 x0 = pack2(xs[3 * (t + 1) + 0], xs[3 * (t + 1) + 0]);
            u64 x1 = pack2(xs[3 * (t + 1) + 1], xs[3 * (t + 1) + 1]);
            u64 x2 = pack2(xs[3 * (t + 1) + 2], xs[3 * (t + 1) + 2]);
            #pragma unroll
            for (int pp = 0; pp < 4; pp++)
                iw[pp] = fma2(x2, wip[2][pp], fma2(x1, wip[1][pp], fma2(x0, wip[0][pp], bip[pp])));
        }

        __syncthreads();   // single barrier per step (ping-pong buffers)

        // combine 8 partial float4s (broadcast LDS, conflict-free)
        float4 c0 = *(const float4*)&red[pb][0][0];
        float4 c1 = *(const float4*)&red[pb][1][0];
        float4 c2 = *(const float4*)&red[pb][2][0];
        float4 c3 = *(const float4*)&red[pb][3][0];
        float4 c4 = *(const float4*)&red[pb][4][0];
        float4 c5 = *(const float4*)&red[pb][5][0];
        float4 c6 = *(const float4*)&red[pb][6][0];
        float4 c7 = *(const float4*)&red[pb][7][0];
        p0 = ((c0.x + c1.x) + (c2.x + c3.x)) + ((c4.x + c5.x) + (c6.x + c7.x));
        p1 = ((c0.y + c1.y) + (c2.y + c3.y)) + ((c4.y + c5.y) + (c6.y + c7.y));
        p2 = ((c0.z + c1.z) + (c2.z + c3.z)) + ((c4.z + c5.z) + (c6.z + c7.z));
        p3 = ((c0.w + c1.w) + (c2.w + c3.w)) + ((c4.w + c5.w) + (c6.w + c7.w));

        if (tid == 0) {
            float4 d0 = *(const float4*)&red[pb][0][4];
            float4 d1 = *(const float4*)&red[pb][1][4];
            float4 d2 = *(const float4*)&red[pb][2][4];
            float4 d3 = *(const float4*)&red[pb][3][4];
            float4 d4 = *(const float4*)&red[pb][4][4];
            float4 d5 = *(const float4*)&red[pb][5][4];
            float4 d6 = *(const float4*)&red[pb][6][4];
            float4 d7 = *(const float4*)&red[pb][7][4];
            float o0 = ((d0.x + d1.x) + (d2.x + d3.x)) + ((d4.x + d5.x) + (d6.x + d7.x)) + bo0;
            float o1 = ((d0.y + d1.y) + (d2.y + d3.y)) + ((d4.y + d5.y) + (d6.y + d7.y)) + bo1;
            float o2 = ((d0.z + d1.z) + (d2.z + d3.z)) + ((d4.z + d5.z) + (d6.z + d7.z)) + bo2;
            outb[(size_t)t * OUT_ + 0] = o0;
            outb[(size_t)t * OUT_ + 1] = o1;
            outb[(size_t)t * OUT_ + 2] = o2;
        }
    }

    // h_last
    *(float4*)(hlast + (size_t)b * HID_ + j0)     = make_float4(h[0], h[1], h[2], h[3]);
    *(float4*)(hlast + (size_t)b * HID_ + j0 + 4) = make_float4(h[4], h[5], h[6], h[7]);
}

extern "C" void kernel_launch(void* const* d_in, const int* in_sizes, int n_in,
                              void* d_out, int out_size) {
    const float* x      = (const float*)d_in[0];
    const float* hidden = (const float*)d_in[1];
    const float* U      = (const float*)d_in[2];
    const float* V      = (const float*)d_in[3];
    const float* Win    = (const float*)d_in[4];
    const float* bin    = (const float*)d_in[5];
    const float* Wout   = (const float*)d_in[6];
    const float* bout   = (const float*)d_in[7];

    float* out   = (float*)d_out;                       // [B,T,OUT]
    float* hlast = out   + (size_t)B_ * T_ * OUT_;      // [B,HID]
    float* rout  = hlast + (size_t)B_ * HID_;           // [B,T,HID]

    low_rank_rnn_kernel<<<B_, TPB>>>(x, hidden, U, V, Win, bin, Wout, bout,
                                     out, hlast, rout);
}